// round 1
// baseline (speedup 1.0000x reference)
#include <cuda_runtime.h>

#define GCN_D     64
#define GCN_C     40
#define GCN_NMAX  100000

// Scratch (device globals: no allocation allowed in kernel_launch)
__device__ float g_dinv[GCN_NMAX];
__device__ float g_tmp[(size_t)GCN_NMAX * GCN_D];   // h @ W
__device__ float g_h[(size_t)GCN_NMAX * GCN_D];     // aggregated output

// ---------------------------------------------------------------------------
// Degree / normalization:  deg[i] = 1 (self loop) + indegree(dst); dinv = rsqrt
// ---------------------------------------------------------------------------
__global__ void k_deg_init(int N) {
    int i = blockIdx.x * blockDim.x + threadIdx.x;
    if (i < N) g_dinv[i] = 1.0f;
}

__global__ void k_deg_count(const int* __restrict__ dst, int E) {
    int e = blockIdx.x * blockDim.x + threadIdx.x;
    if (e < E) atomicAdd(&g_dinv[dst[e]], 1.0f);
}

__global__ void k_deg_finish(int N) {
    int i = blockIdx.x * blockDim.x + threadIdx.x;
    if (i < N) g_dinv[i] = rsqrtf(g_dinv[i]);
}

// ---------------------------------------------------------------------------
// g_tmp = X @ W   (X: [N,64] = external input or g_h; W: [64,64])
// One thread per node row; W staged in smem; all lanes read the same W word
// per step -> broadcast (conflict-free).
// ---------------------------------------------------------------------------
__global__ __launch_bounds__(128) void k_gemm64(const float* __restrict__ Xext,
                                                const float* __restrict__ W,
                                                int N, int use_h) {
    __shared__ float4 Ws[GCN_D * 16];   // 64 rows x 16 float4 = 64x64 floats
    for (int i = threadIdx.x; i < GCN_D * 16; i += blockDim.x)
        Ws[i] = ((const float4*)W)[i];
    __syncthreads();

    int n = blockIdx.x * blockDim.x + threadIdx.x;
    if (n >= N) return;

    const float* X = use_h ? g_h : Xext;
    const float4* xr = (const float4*)(X + (size_t)n * GCN_D);

    float4 acc[16];
#pragma unroll
    for (int j = 0; j < 16; j++) acc[j] = make_float4(0.f, 0.f, 0.f, 0.f);

#pragma unroll 4
    for (int k4 = 0; k4 < 16; k4++) {
        float4 xv = xr[k4];
#pragma unroll
        for (int j4 = 0; j4 < 16; j4++) {
            float4 w;
            w = Ws[(4 * k4 + 0) * 16 + j4];
            acc[j4].x = fmaf(xv.x, w.x, acc[j4].x);
            acc[j4].y = fmaf(xv.x, w.y, acc[j4].y);
            acc[j4].z = fmaf(xv.x, w.z, acc[j4].z);
            acc[j4].w = fmaf(xv.x, w.w, acc[j4].w);
            w = Ws[(4 * k4 + 1) * 16 + j4];
            acc[j4].x = fmaf(xv.y, w.x, acc[j4].x);
            acc[j4].y = fmaf(xv.y, w.y, acc[j4].y);
            acc[j4].z = fmaf(xv.y, w.z, acc[j4].z);
            acc[j4].w = fmaf(xv.y, w.w, acc[j4].w);
            w = Ws[(4 * k4 + 2) * 16 + j4];
            acc[j4].x = fmaf(xv.z, w.x, acc[j4].x);
            acc[j4].y = fmaf(xv.z, w.y, acc[j4].y);
            acc[j4].z = fmaf(xv.z, w.z, acc[j4].z);
            acc[j4].w = fmaf(xv.z, w.w, acc[j4].w);
            w = Ws[(4 * k4 + 3) * 16 + j4];
            acc[j4].x = fmaf(xv.w, w.x, acc[j4].x);
            acc[j4].y = fmaf(xv.w, w.y, acc[j4].y);
            acc[j4].z = fmaf(xv.w, w.z, acc[j4].z);
            acc[j4].w = fmaf(xv.w, w.w, acc[j4].w);
        }
    }

    float4* yr = (float4*)(g_tmp + (size_t)n * GCN_D);
#pragma unroll
    for (int j = 0; j < 16; j++) yr[j] = acc[j];
}

// ---------------------------------------------------------------------------
// g_h[i] = g_tmp[i] * dinv[i]^2   (self-loop contribution; also initializes h)
// ---------------------------------------------------------------------------
__global__ void k_self_init(int N) {
    int t = blockIdx.x * blockDim.x + threadIdx.x;
    if (t >= N * 16) return;
    int n = t >> 4;
    int d = t & 15;
    float s = g_dinv[n];
    s = s * s;
    float4 v = ((const float4*)(g_tmp + (size_t)n * GCN_D))[d];
    v.x *= s; v.y *= s; v.z *= s; v.w *= s;
    ((float4*)(g_h + (size_t)n * GCN_D))[d] = v;
}

// ---------------------------------------------------------------------------
// Edge scatter: h[dst] += tmp[src] * dinv[src] * dinv[dst]
// 16 threads per edge, each handling 4 contiguous dims (float4 gather,
// 4 scalar REDG atomics).
// ---------------------------------------------------------------------------
__global__ void k_scatter(const int* __restrict__ src, const int* __restrict__ dst,
                          int E) {
    int t = blockIdx.x * blockDim.x + threadIdx.x;
    int e = t >> 4;
    if (e >= E) return;
    int d = (t & 15) << 2;
    int s = src[e];
    int q = dst[e];
    float nrm = g_dinv[s] * g_dinv[q];
    float4 v = *(const float4*)(g_tmp + (size_t)s * GCN_D + d);
    float* hp = g_h + (size_t)q * GCN_D + d;
    atomicAdd(hp + 0, v.x * nrm);
    atomicAdd(hp + 1, v.y * nrm);
    atomicAdd(hp + 2, v.z * nrm);
    atomicAdd(hp + 3, v.w * nrm);
}

// ---------------------------------------------------------------------------
// g_h = relu(g_h + b)
// ---------------------------------------------------------------------------
__global__ void k_bias_relu(const float* __restrict__ b, int N) {
    int t = blockIdx.x * blockDim.x + threadIdx.x;
    if (t >= N * 16) return;
    int n = t >> 4;
    int d = t & 15;
    float4 bv = ((const float4*)b)[d];
    float4 v = ((const float4*)(g_h + (size_t)n * GCN_D))[d];
    v.x = fmaxf(v.x + bv.x, 0.f);
    v.y = fmaxf(v.y + bv.y, 0.f);
    v.z = fmaxf(v.z + bv.z, 0.f);
    v.w = fmaxf(v.w + bv.w, 0.f);
    ((float4*)(g_h + (size_t)n * GCN_D))[d] = v;
}

// ---------------------------------------------------------------------------
// Classifier + log_softmax: out[n] = log_softmax(g_h[n] @ Wc + bc)
// One thread per node; Wc (64x40) + bc in smem.
// ---------------------------------------------------------------------------
__global__ __launch_bounds__(128) void k_classify(const float* __restrict__ Wc,
                                                  const float* __restrict__ bc,
                                                  float* __restrict__ out, int N) {
    __shared__ float4 Ws[GCN_D * 10];   // 64 rows x 10 float4 = 64x40
    __shared__ float bs[GCN_C];
    for (int i = threadIdx.x; i < GCN_D * 10; i += blockDim.x)
        Ws[i] = ((const float4*)Wc)[i];
    for (int i = threadIdx.x; i < GCN_C; i += blockDim.x)
        bs[i] = bc[i];
    __syncthreads();

    int n = blockIdx.x * blockDim.x + threadIdx.x;
    if (n >= N) return;

    float4 acc[10];
#pragma unroll
    for (int c = 0; c < 10; c++)
        acc[c] = make_float4(bs[4 * c + 0], bs[4 * c + 1], bs[4 * c + 2], bs[4 * c + 3]);

    const float4* hr = (const float4*)(g_h + (size_t)n * GCN_D);
#pragma unroll 4
    for (int k4 = 0; k4 < 16; k4++) {
        float4 xv = hr[k4];
        const float xs[4] = {xv.x, xv.y, xv.z, xv.w};
#pragma unroll
        for (int kk = 0; kk < 4; kk++) {
            float xk = xs[kk];
            int k = 4 * k4 + kk;
#pragma unroll
            for (int c = 0; c < 10; c++) {
                float4 w = Ws[k * 10 + c];
                acc[c].x = fmaf(xk, w.x, acc[c].x);
                acc[c].y = fmaf(xk, w.y, acc[c].y);
                acc[c].z = fmaf(xk, w.z, acc[c].z);
                acc[c].w = fmaf(xk, w.w, acc[c].w);
            }
        }
    }

    float* a = (float*)acc;
    float m = a[0];
#pragma unroll
    for (int c = 1; c < GCN_C; c++) m = fmaxf(m, a[c]);
    float sum = 0.f;
#pragma unroll
    for (int c = 0; c < GCN_C; c++) sum += expf(a[c] - m);
    float lse = logf(sum) + m;
    float* op = out + (size_t)n * GCN_C;
#pragma unroll
    for (int c = 0; c < GCN_C; c++) op[c] = a[c] - lse;
}

// ---------------------------------------------------------------------------
// Launch
// ---------------------------------------------------------------------------
extern "C" void kernel_launch(void* const* d_in, const int* in_sizes, int n_in,
                              void* d_out, int out_size) {
    const float* x  = (const float*)d_in[0];
    const int*   ei = (const int*)d_in[1];
    const float* W0 = (const float*)d_in[2];
    const float* b0 = (const float*)d_in[3];
    const float* W1 = (const float*)d_in[4];
    const float* b1 = (const float*)d_in[5];
    const float* W2 = (const float*)d_in[6];
    const float* b2 = (const float*)d_in[7];
    const float* Wc = (const float*)d_in[8];
    const float* bc = (const float*)d_in[9];
    float* out = (float*)d_out;

    int N = in_sizes[0] / GCN_D;
    int E = in_sizes[1] / 2;
    const int* src = ei;
    const int* dst = ei + E;

    int nb_n   = (N + 255) / 256;
    int nb_e   = (E + 255) / 256;
    int nb_n16 = (N * 16 + 255) / 256;
    int nb_e16 = (int)(((long long)E * 16 + 255) / 256);
    int nb_g   = (N + 127) / 128;

    // degree / dinv (uses dst only, per reference)
    k_deg_init<<<nb_n, 256>>>(N);
    k_deg_count<<<nb_e, 256>>>(dst, E);
    k_deg_finish<<<nb_n, 256>>>(N);

    // layer 0
    k_gemm64<<<nb_g, 128>>>(x, W0, N, 0);
    k_self_init<<<nb_n16, 256>>>(N);
    k_scatter<<<nb_e16, 256>>>(src, dst, E);
    k_bias_relu<<<nb_n16, 256>>>(b0, N);

    // layer 1
    k_gemm64<<<nb_g, 128>>>(x, W1, N, 1);
    k_self_init<<<nb_n16, 256>>>(N);
    k_scatter<<<nb_e16, 256>>>(src, dst, E);
    k_bias_relu<<<nb_n16, 256>>>(b1, N);

    // layer 2
    k_gemm64<<<nb_g, 128>>>(x, W2, N, 1);
    k_self_init<<<nb_n16, 256>>>(N);
    k_scatter<<<nb_e16, 256>>>(src, dst, E);
    k_bias_relu<<<nb_n16, 256>>>(b2, N);

    // classifier + log_softmax
    k_classify<<<nb_g, 128>>>(Wc, bc, out, N);
}

// round 2
// speedup vs baseline: 1.7969x; 1.7969x over previous
#include <cuda_runtime.h>

#define GCN_D     64
#define GCN_C     40
#define GCN_NMAX  100000
#define GCN_EMAX  800000
#define SCAN_T    1024

// Scratch (device globals: no allocation allowed in kernel_launch)
__device__ float g_dinv[GCN_NMAX];
__device__ float g_tmp[(size_t)GCN_NMAX * GCN_D];   // h @ W
__device__ float g_h[(size_t)GCN_NMAX * GCN_D];     // aggregated output
__device__ int   g_cnt[GCN_NMAX];                   // in-degree (excl. self)
__device__ int   g_off[GCN_NMAX];                   // CSR row offsets (exclusive scan)
__device__ int   g_cur[GCN_NMAX];                   // fill cursors
__device__ int   g_bsum[256];                       // block sums for scan
__device__ int   g_csrc[GCN_EMAX];                  // CSR column (src node)
__device__ float g_cnorm[GCN_EMAX];                 // per-edge norm dinv[s]*dinv[d]

// ---------------------------------------------------------------------------
// CSR build
// ---------------------------------------------------------------------------
__global__ void k_zero(int N) {
    int i = blockIdx.x * blockDim.x + threadIdx.x;
    if (i < N) { g_cnt[i] = 0; g_cur[i] = 0; }
}

__global__ void k_count(const int* __restrict__ dst, int E) {
    int e = blockIdx.x * blockDim.x + threadIdx.x;
    if (e < E) atomicAdd(&g_cnt[dst[e]], 1);
}

__global__ void k_dinv(int N) {
    int i = blockIdx.x * blockDim.x + threadIdx.x;
    if (i < N) g_dinv[i] = rsqrtf((float)(g_cnt[i] + 1));  // +1 self loop
}

__global__ void k_scan1(int N) {
    __shared__ int sh[SCAN_T];
    int t = threadIdx.x;
    int idx = blockIdx.x * SCAN_T + t;
    int v = (idx < N) ? g_cnt[idx] : 0;
    sh[t] = v;
    __syncthreads();
    for (int o = 1; o < SCAN_T; o <<= 1) {
        int a = (t >= o) ? sh[t - o] : 0;
        __syncthreads();
        sh[t] += a;
        __syncthreads();
    }
    if (idx < N) g_off[idx] = sh[t] - v;           // exclusive within block
    if (t == SCAN_T - 1) g_bsum[blockIdx.x] = sh[t];
}

__global__ void k_scan2(int nb) {
    __shared__ int sh[256];
    int t = threadIdx.x;
    int v = (t < nb) ? g_bsum[t] : 0;
    sh[t] = v;
    __syncthreads();
    for (int o = 1; o < 256; o <<= 1) {
        int a = (t >= o) ? sh[t - o] : 0;
        __syncthreads();
        sh[t] += a;
        __syncthreads();
    }
    if (t < nb) g_bsum[t] = sh[t] - v;             // exclusive block offsets
}

__global__ void k_scan3(int N) {
    int i = blockIdx.x * blockDim.x + threadIdx.x;
    if (i < N) g_off[i] += g_bsum[i >> 10];
}

__global__ void k_fill(const int* __restrict__ src, const int* __restrict__ dst,
                       int E) {
    int e = blockIdx.x * blockDim.x + threadIdx.x;
    if (e >= E) return;
    int d = dst[e];
    int s = src[e];
    int pos = g_off[d] + atomicAdd(&g_cur[d], 1);
    g_csrc[pos] = s;
    g_cnorm[pos] = g_dinv[s] * g_dinv[d];
}

// ---------------------------------------------------------------------------
// g_tmp = X @ W   (X: [N,64] = external input or g_h; W: [64,64])
// ---------------------------------------------------------------------------
__global__ __launch_bounds__(128) void k_gemm64(const float* __restrict__ Xext,
                                                const float* __restrict__ W,
                                                int N, int use_h) {
    __shared__ float4 Ws[GCN_D * 16];   // 64 rows x 16 float4
    for (int i = threadIdx.x; i < GCN_D * 16; i += blockDim.x)
        Ws[i] = ((const float4*)W)[i];
    __syncthreads();

    int n = blockIdx.x * blockDim.x + threadIdx.x;
    if (n >= N) return;

    const float* X = use_h ? g_h : Xext;
    const float4* xr = (const float4*)(X + (size_t)n * GCN_D);

    float4 acc[16];
#pragma unroll
    for (int j = 0; j < 16; j++) acc[j] = make_float4(0.f, 0.f, 0.f, 0.f);

#pragma unroll 4
    for (int k4 = 0; k4 < 16; k4++) {
        float4 xv = xr[k4];
#pragma unroll
        for (int j4 = 0; j4 < 16; j4++) {
            float4 w;
            w = Ws[(4 * k4 + 0) * 16 + j4];
            acc[j4].x = fmaf(xv.x, w.x, acc[j4].x);
            acc[j4].y = fmaf(xv.x, w.y, acc[j4].y);
            acc[j4].z = fmaf(xv.x, w.z, acc[j4].z);
            acc[j4].w = fmaf(xv.x, w.w, acc[j4].w);
            w = Ws[(4 * k4 + 1) * 16 + j4];
            acc[j4].x = fmaf(xv.y, w.x, acc[j4].x);
            acc[j4].y = fmaf(xv.y, w.y, acc[j4].y);
            acc[j4].z = fmaf(xv.y, w.z, acc[j4].z);
            acc[j4].w = fmaf(xv.y, w.w, acc[j4].w);
            w = Ws[(4 * k4 + 2) * 16 + j4];
            acc[j4].x = fmaf(xv.z, w.x, acc[j4].x);
            acc[j4].y = fmaf(xv.z, w.y, acc[j4].y);
            acc[j4].z = fmaf(xv.z, w.z, acc[j4].z);
            acc[j4].w = fmaf(xv.z, w.w, acc[j4].w);
            w = Ws[(4 * k4 + 3) * 16 + j4];
            acc[j4].x = fmaf(xv.w, w.x, acc[j4].x);
            acc[j4].y = fmaf(xv.w, w.y, acc[j4].y);
            acc[j4].z = fmaf(xv.w, w.z, acc[j4].z);
            acc[j4].w = fmaf(xv.w, w.w, acc[j4].w);
        }
    }

    float4* yr = (float4*)(g_tmp + (size_t)n * GCN_D);
#pragma unroll
    for (int j = 0; j < 16; j++) yr[j] = acc[j];
}

// ---------------------------------------------------------------------------
// Fused aggregation: h[i] = relu( sum_{e: dst=i} tmp[src]*norm
//                                 + tmp[i]*dinv[i]^2 + b )
// One warp per node; lane handles float2 chunk (64 floats = 32 lanes x 2).
// Edge indices/norms loaded 32-wide then broadcast via shfl.
// ---------------------------------------------------------------------------
__global__ __launch_bounds__(256) void k_agg(const float* __restrict__ b, int N) {
    int w = (blockIdx.x * blockDim.x + threadIdx.x) >> 5;
    if (w >= N) return;
    int lane = threadIdx.x & 31;

    const float2* tmp2 = (const float2*)g_tmp;
    float di = g_dinv[w];
    float2 acc = tmp2[(size_t)w * 32 + lane];
    float s2 = di * di;
    acc.x *= s2; acc.y *= s2;

    int off = g_off[w];
    int cnt = g_cnt[w];
    for (int j0 = 0; j0 < cnt; j0 += 32) {
        int m = min(32, cnt - j0);
        int s = 0; float nm = 0.f;
        if (lane < m) {
            s  = g_csrc[off + j0 + lane];
            nm = g_cnorm[off + j0 + lane];
        }
        for (int j = 0; j < m; j++) {
            int   ss = __shfl_sync(0xffffffffu, s, j);
            float nn = __shfl_sync(0xffffffffu, nm, j);
            float2 v = tmp2[(size_t)ss * 32 + lane];
            acc.x = fmaf(v.x, nn, acc.x);
            acc.y = fmaf(v.y, nn, acc.y);
        }
    }

    float2 bv = ((const float2*)b)[lane];
    acc.x = fmaxf(acc.x + bv.x, 0.f);
    acc.y = fmaxf(acc.y + bv.y, 0.f);
    ((float2*)g_h)[(size_t)w * 32 + lane] = acc;
}

// ---------------------------------------------------------------------------
// Classifier + log_softmax
// ---------------------------------------------------------------------------
__global__ __launch_bounds__(128) void k_classify(const float* __restrict__ Wc,
                                                  const float* __restrict__ bc,
                                                  float* __restrict__ out, int N) {
    __shared__ float4 Ws[GCN_D * 10];   // 64 x 40
    __shared__ float bs[GCN_C];
    for (int i = threadIdx.x; i < GCN_D * 10; i += blockDim.x)
        Ws[i] = ((const float4*)Wc)[i];
    for (int i = threadIdx.x; i < GCN_C; i += blockDim.x)
        bs[i] = bc[i];
    __syncthreads();

    int n = blockIdx.x * blockDim.x + threadIdx.x;
    if (n >= N) return;

    float4 acc[10];
#pragma unroll
    for (int c = 0; c < 10; c++)
        acc[c] = make_float4(bs[4 * c + 0], bs[4 * c + 1], bs[4 * c + 2], bs[4 * c + 3]);

    const float4* hr = (const float4*)(g_h + (size_t)n * GCN_D);
#pragma unroll 4
    for (int k4 = 0; k4 < 16; k4++) {
        float4 xv = hr[k4];
        const float xs[4] = {xv.x, xv.y, xv.z, xv.w};
#pragma unroll
        for (int kk = 0; kk < 4; kk++) {
            float xk = xs[kk];
            int k = 4 * k4 + kk;
#pragma unroll
            for (int c = 0; c < 10; c++) {
                float4 w = Ws[k * 10 + c];
                acc[c].x = fmaf(xk, w.x, acc[c].x);
                acc[c].y = fmaf(xk, w.y, acc[c].y);
                acc[c].z = fmaf(xk, w.z, acc[c].z);
                acc[c].w = fmaf(xk, w.w, acc[c].w);
            }
        }
    }

    float* a = (float*)acc;
    float m = a[0];
#pragma unroll
    for (int c = 1; c < GCN_C; c++) m = fmaxf(m, a[c]);
    float sum = 0.f;
#pragma unroll
    for (int c = 0; c < GCN_C; c++) sum += expf(a[c] - m);
    float lse = logf(sum) + m;
    float* op = out + (size_t)n * GCN_C;
#pragma unroll
    for (int c = 0; c < GCN_C; c++) op[c] = a[c] - lse;
}

// ---------------------------------------------------------------------------
// Launch
// ---------------------------------------------------------------------------
extern "C" void kernel_launch(void* const* d_in, const int* in_sizes, int n_in,
                              void* d_out, int out_size) {
    const float* x  = (const float*)d_in[0];
    const int*   ei = (const int*)d_in[1];
    const float* W0 = (const float*)d_in[2];
    const float* b0 = (const float*)d_in[3];
    const float* W1 = (const float*)d_in[4];
    const float* b1 = (const float*)d_in[5];
    const float* W2 = (const float*)d_in[6];
    const float* b2 = (const float*)d_in[7];
    const float* Wc = (const float*)d_in[8];
    const float* bc = (const float*)d_in[9];
    float* out = (float*)d_out;

    int N = in_sizes[0] / GCN_D;
    int E = in_sizes[1] / 2;
    const int* src = ei;
    const int* dst = ei + E;

    int nb_n  = (N + 255) / 256;
    int nb_e  = (E + 255) / 256;
    int nb_g  = (N + 127) / 128;
    int nb_s  = (N + SCAN_T - 1) / SCAN_T;
    int nb_w  = (int)(((long long)N * 32 + 255) / 256);

    // CSR build + dinv
    k_zero<<<nb_n, 256>>>(N);
    k_count<<<nb_e, 256>>>(dst, E);
    k_dinv<<<nb_n, 256>>>(N);
    k_scan1<<<nb_s, SCAN_T>>>(N);
    k_scan2<<<1, 256>>>(nb_s);
    k_scan3<<<nb_n, 256>>>(N);
    k_fill<<<nb_e, 256>>>(src, dst, E);

    // layer 0
    k_gemm64<<<nb_g, 128>>>(x, W0, N, 0);
    k_agg<<<nb_w, 256>>>(b0, N);

    // layer 1
    k_gemm64<<<nb_g, 128>>>(x, W1, N, 1);
    k_agg<<<nb_w, 256>>>(b1, N);

    // layer 2
    k_gemm64<<<nb_g, 128>>>(x, W2, N, 1);
    k_agg<<<nb_w, 256>>>(b2, N);

    // classifier + log_softmax
    k_classify<<<nb_g, 128>>>(Wc, bc, out, N);
}

// round 3
// speedup vs baseline: 1.8250x; 1.0156x over previous
#include <cuda_runtime.h>

#define GCN_D     64
#define GCN_C     40
#define GCN_NMAX  100000
#define GCN_EMAX  800000
#define SCAN_T    1024

typedef unsigned long long u64;

// Scratch (device globals: no allocation allowed in kernel_launch)
__device__ float g_dinv[GCN_NMAX];
__device__ float g_tmp[(size_t)GCN_NMAX * GCN_D];   // h @ W
__device__ float g_h[(size_t)GCN_NMAX * GCN_D];     // aggregated output
__device__ int   g_cnt[GCN_NMAX];                   // in-degree (excl. self)
__device__ int   g_off[GCN_NMAX];                   // CSR row offsets
__device__ int   g_cur[GCN_NMAX];                   // fill cursors
__device__ int   g_bsum[256];                       // block sums for scan
__device__ int   g_csrc[GCN_EMAX];                  // CSR column (src node)
__device__ float g_cnorm[GCN_EMAX];                 // per-edge norm

// ---------------------------------------------------------------------------
// Packed fp32x2 helpers (sm_103a; ptxas never emits FFMA2 from plain C++)
// ---------------------------------------------------------------------------
__device__ __forceinline__ u64 ffma2(u64 a, u64 b, u64 c) {
    u64 d;
    asm("fma.rn.f32x2 %0, %1, %2, %3;" : "=l"(d) : "l"(a), "l"(b), "l"(c));
    return d;
}
__device__ __forceinline__ u64 pack2(float v) {
    u64 r;
    asm("mov.b64 %0, {%1, %1};" : "=l"(r) : "f"(v));
    return r;
}

// ---------------------------------------------------------------------------
// CSR build
// ---------------------------------------------------------------------------
__global__ void k_zero(int N) {
    int i = blockIdx.x * blockDim.x + threadIdx.x;
    if (i < N) { g_cnt[i] = 0; g_cur[i] = 0; }
}

__global__ void k_count(const int* __restrict__ dst, int E) {
    int e = blockIdx.x * blockDim.x + threadIdx.x;
    if (e < E) atomicAdd(&g_cnt[dst[e]], 1);
}

__global__ void k_dinv(int N) {
    int i = blockIdx.x * blockDim.x + threadIdx.x;
    if (i < N) g_dinv[i] = rsqrtf((float)(g_cnt[i] + 1));  // +1 self loop
}

__global__ void k_scan1(int N) {
    __shared__ int sh[SCAN_T];
    int t = threadIdx.x;
    int idx = blockIdx.x * SCAN_T + t;
    int v = (idx < N) ? g_cnt[idx] : 0;
    sh[t] = v;
    __syncthreads();
    for (int o = 1; o < SCAN_T; o <<= 1) {
        int a = (t >= o) ? sh[t - o] : 0;
        __syncthreads();
        sh[t] += a;
        __syncthreads();
    }
    if (idx < N) g_off[idx] = sh[t] - v;
    if (t == SCAN_T - 1) g_bsum[blockIdx.x] = sh[t];
}

__global__ void k_scan2(int nb) {
    __shared__ int sh[256];
    int t = threadIdx.x;
    int v = (t < nb) ? g_bsum[t] : 0;
    sh[t] = v;
    __syncthreads();
    for (int o = 1; o < 256; o <<= 1) {
        int a = (t >= o) ? sh[t - o] : 0;
        __syncthreads();
        sh[t] += a;
        __syncthreads();
    }
    if (t < nb) g_bsum[t] = sh[t] - v;
}

__global__ void k_scan3(int N) {
    int i = blockIdx.x * blockDim.x + threadIdx.x;
    if (i < N) g_off[i] += g_bsum[i >> 10];
}

__global__ void k_fill(const int* __restrict__ src, const int* __restrict__ dst,
                       int E) {
    int e = blockIdx.x * blockDim.x + threadIdx.x;
    if (e >= E) return;
    int d = dst[e];
    int s = src[e];
    int pos = g_off[d] + atomicAdd(&g_cur[d], 1);
    g_csrc[pos] = s;
    g_cnorm[pos] = g_dinv[s] * g_dinv[d];
}

// ---------------------------------------------------------------------------
// g_tmp = X @ W  via packed fp32x2 FMA. One thread per node row.
// W staged in smem as ulonglong2 (pair-pairs); broadcast LDS (conflict-free).
// ---------------------------------------------------------------------------
__global__ __launch_bounds__(128) void k_gemm64(const float* __restrict__ Xext,
                                                const float* __restrict__ W,
                                                int N, int use_h) {
    __shared__ ulonglong2 Ws[GCN_D * 16];   // 64 rows x 16 ull2 (= 64 floats)
    for (int i = threadIdx.x; i < GCN_D * 16; i += blockDim.x)
        Ws[i] = ((const ulonglong2*)W)[i];
    __syncthreads();

    int n = blockIdx.x * blockDim.x + threadIdx.x;
    if (n >= N) return;

    const float* X = use_h ? g_h : Xext;
    const float4* xr = (const float4*)(X + (size_t)n * GCN_D);

    u64 acc[32];
#pragma unroll
    for (int j = 0; j < 32; j++) acc[j] = 0ull;

#pragma unroll 2
    for (int k4 = 0; k4 < 16; k4++) {
        float4 xv = xr[k4];
        const float xs[4] = {xv.x, xv.y, xv.z, xv.w};
#pragma unroll
        for (int kk = 0; kk < 4; kk++) {
            u64 xx = pack2(xs[kk]);
            int k = 4 * k4 + kk;
#pragma unroll
            for (int p4 = 0; p4 < 16; p4++) {
                ulonglong2 w = Ws[k * 16 + p4];
                acc[2 * p4 + 0] = ffma2(xx, w.x, acc[2 * p4 + 0]);
                acc[2 * p4 + 1] = ffma2(xx, w.y, acc[2 * p4 + 1]);
            }
        }
    }

    ulonglong2* yr = (ulonglong2*)(g_tmp + (size_t)n * GCN_D);
#pragma unroll
    for (int j = 0; j < 16; j++) {
        ulonglong2 v;
        v.x = acc[2 * j];
        v.y = acc[2 * j + 1];
        yr[j] = v;
    }
}

// ---------------------------------------------------------------------------
// Fused aggregation: h[i] = relu( sum_{e: dst=i} tmp[src]*norm
//                                 + tmp[i]*dinv[i]^2 + b )
// One warp per node; lane handles float2. Inner gather loop unrolled 4x
// so four independent L2 gathers are in flight.
// ---------------------------------------------------------------------------
__global__ __launch_bounds__(256) void k_agg(const float* __restrict__ b, int N) {
    int w = (blockIdx.x * blockDim.x + threadIdx.x) >> 5;
    if (w >= N) return;
    int lane = threadIdx.x & 31;

    const float2* __restrict__ tmp2 = (const float2*)g_tmp;
    float di = g_dinv[w];
    float2 acc = tmp2[(size_t)w * 32 + lane];
    float s2 = di * di;
    acc.x *= s2; acc.y *= s2;

    int off = g_off[w];
    int cnt = g_cnt[w];
    for (int j0 = 0; j0 < cnt; j0 += 32) {
        int m = min(32, cnt - j0);
        int s = 0; float nm = 0.f;
        if (lane < m) {
            s  = g_csrc[off + j0 + lane];
            nm = g_cnorm[off + j0 + lane];
        }
        int j = 0;
        for (; j + 4 <= m; j += 4) {
            int   s0 = __shfl_sync(0xffffffffu, s, j + 0);
            int   s1 = __shfl_sync(0xffffffffu, s, j + 1);
            int   s2i = __shfl_sync(0xffffffffu, s, j + 2);
            int   s3 = __shfl_sync(0xffffffffu, s, j + 3);
            float n0 = __shfl_sync(0xffffffffu, nm, j + 0);
            float n1 = __shfl_sync(0xffffffffu, nm, j + 1);
            float n2 = __shfl_sync(0xffffffffu, nm, j + 2);
            float n3 = __shfl_sync(0xffffffffu, nm, j + 3);
            float2 v0 = tmp2[(size_t)s0 * 32 + lane];
            float2 v1 = tmp2[(size_t)s1 * 32 + lane];
            float2 v2 = tmp2[(size_t)s2i * 32 + lane];
            float2 v3 = tmp2[(size_t)s3 * 32 + lane];
            acc.x = fmaf(v0.x, n0, acc.x); acc.y = fmaf(v0.y, n0, acc.y);
            acc.x = fmaf(v1.x, n1, acc.x); acc.y = fmaf(v1.y, n1, acc.y);
            acc.x = fmaf(v2.x, n2, acc.x); acc.y = fmaf(v2.y, n2, acc.y);
            acc.x = fmaf(v3.x, n3, acc.x); acc.y = fmaf(v3.y, n3, acc.y);
        }
        for (; j < m; j++) {
            int   ss = __shfl_sync(0xffffffffu, s, j);
            float nn = __shfl_sync(0xffffffffu, nm, j);
            float2 v = tmp2[(size_t)ss * 32 + lane];
            acc.x = fmaf(v.x, nn, acc.x);
            acc.y = fmaf(v.y, nn, acc.y);
        }
    }

    float2 bv = ((const float2*)b)[lane];
    acc.x = fmaxf(acc.x + bv.x, 0.f);
    acc.y = fmaxf(acc.y + bv.y, 0.f);
    ((float2*)g_h)[(size_t)w * 32 + lane] = acc;
}

// ---------------------------------------------------------------------------
// Classifier + log_softmax (packed fp32x2)
// ---------------------------------------------------------------------------
__global__ __launch_bounds__(128) void k_classify(const float* __restrict__ Wc,
                                                  const float* __restrict__ bc,
                                                  float* __restrict__ out, int N) {
    __shared__ ulonglong2 Ws[GCN_D * 10];   // 64 rows x 10 ull2 (= 40 floats)
    __shared__ float bs[GCN_C];
    for (int i = threadIdx.x; i < GCN_D * 10; i += blockDim.x)
        Ws[i] = ((const ulonglong2*)Wc)[i];
    for (int i = threadIdx.x; i < GCN_C; i += blockDim.x)
        bs[i] = bc[i];
    __syncthreads();

    int n = blockIdx.x * blockDim.x + threadIdx.x;
    if (n >= N) return;

    u64 acc[20];
    {
        const u64* bp = (const u64*)bs;
#pragma unroll
        for (int c = 0; c < 20; c++) acc[c] = bp[c];
    }

    const float4* hr = (const float4*)(g_h + (size_t)n * GCN_D);
#pragma unroll 4
    for (int k4 = 0; k4 < 16; k4++) {
        float4 xv = hr[k4];
        const float xs[4] = {xv.x, xv.y, xv.z, xv.w};
#pragma unroll
        for (int kk = 0; kk < 4; kk++) {
            u64 xx = pack2(xs[kk]);
            int k = 4 * k4 + kk;
#pragma unroll
            for (int c = 0; c < 10; c++) {
                ulonglong2 w = Ws[k * 10 + c];
                acc[2 * c + 0] = ffma2(xx, w.x, acc[2 * c + 0]);
                acc[2 * c + 1] = ffma2(xx, w.y, acc[2 * c + 1]);
            }
        }
    }

    float a[GCN_C];
#pragma unroll
    for (int c = 0; c < 20; c++) {
        a[2 * c]     = __uint_as_float((unsigned)(acc[c] & 0xffffffffu));
        a[2 * c + 1] = __uint_as_float((unsigned)(acc[c] >> 32));
    }
    float m = a[0];
#pragma unroll
    for (int c = 1; c < GCN_C; c++) m = fmaxf(m, a[c]);
    float sum = 0.f;
#pragma unroll
    for (int c = 0; c < GCN_C; c++) sum += expf(a[c] - m);
    float lse = logf(sum) + m;
    float* op = out + (size_t)n * GCN_C;
#pragma unroll
    for (int c = 0; c < GCN_C; c++) op[c] = a[c] - lse;
}

// ---------------------------------------------------------------------------
// Launch
// ---------------------------------------------------------------------------
extern "C" void kernel_launch(void* const* d_in, const int* in_sizes, int n_in,
                              void* d_out, int out_size) {
    const float* x  = (const float*)d_in[0];
    const int*   ei = (const int*)d_in[1];
    const float* W0 = (const float*)d_in[2];
    const float* b0 = (const float*)d_in[3];
    const float* W1 = (const float*)d_in[4];
    const float* b1 = (const float*)d_in[5];
    const float* W2 = (const float*)d_in[6];
    const float* b2 = (const float*)d_in[7];
    const float* Wc = (const float*)d_in[8];
    const float* bc = (const float*)d_in[9];
    float* out = (float*)d_out;

    int N = in_sizes[0] / GCN_D;
    int E = in_sizes[1] / 2;
    const int* src = ei;
    const int* dst = ei + E;

    int nb_n  = (N + 255) / 256;
    int nb_e  = (E + 255) / 256;
    int nb_g  = (N + 127) / 128;
    int nb_s  = (N + SCAN_T - 1) / SCAN_T;
    int nb_w  = (int)(((long long)N * 32 + 255) / 256);

    // CSR build + dinv
    k_zero<<<nb_n, 256>>>(N);
    k_count<<<nb_e, 256>>>(dst, E);
    k_dinv<<<nb_n, 256>>>(N);
    k_scan1<<<nb_s, SCAN_T>>>(N);
    k_scan2<<<1, 256>>>(nb_s);
    k_scan3<<<nb_n, 256>>>(N);
    k_fill<<<nb_e, 256>>>(src, dst, E);

    // layer 0
    k_gemm64<<<nb_g, 128>>>(x, W0, N, 0);
    k_agg<<<nb_w, 256>>>(b0, N);

    // layer 1
    k_gemm64<<<nb_g, 128>>>(x, W1, N, 1);
    k_agg<<<nb_w, 256>>>(b1, N);

    // layer 2
    k_gemm64<<<nb_g, 128>>>(x, W2, N, 1);
    k_agg<<<nb_w, 256>>>(b2, N);

    // classifier + log_softmax
    k_classify<<<nb_g, 128>>>(Wc, bc, out, N);
}